// round 2
// baseline (speedup 1.0000x reference)
#include <cuda_runtime.h>

#define NN 50000
#define EE 1600000
#define BM 128
#define BN 128
#define BK 16

// ---------------- device scratch (no allocs allowed) ----------------
__device__ __align__(256) float g_ma[NN * 128];
__device__ __align__(256) float g_mb[NN * 128];
__device__ __align__(256) float g_ga[NN * 128];
__device__ __align__(256) float g_gb[NN * 128];
__device__ __align__(256) float g_h[NN * 128];
__device__ __align__(256) float g_t[NN * 128];
__device__ __align__(256) float g_comb[NN * 128];
__device__ int   g_cnt[NN];
__device__ float g_dinv[NN];
__device__ int   g_rowptr[NN + 1];
__device__ int   g_cur[NN];
__device__ int   g_srcidx[EE];
__device__ int   g_is64;

// ---------------- edge-index dtype detection ----------------
// int64 node-ids in [0, 50000): every odd 32-bit word (high half, little-endian)
// is zero. int32 random node-ids: odd words are random values, ~never zero.
__global__ void detect_kernel(const unsigned int* __restrict__ w) {
    if (threadIdx.x == 0 && blockIdx.x == 0) {
        int zeros = 0;
        for (int i = 1; i < 512; i += 2) zeros += (w[i] == 0u) ? 1 : 0;
        g_is64 = (zeros >= 200) ? 1 : 0;
    }
}

__device__ __forceinline__ int load_idx(const void* ei, long long pos, int is64) {
    if (is64) return (int)((const long long*)ei)[pos];
    return ((const int*)ei)[pos];
}

// ---------------- packed f32x2 FMA helpers ----------------
#define FMA2(acc, a, b) asm("fma.rn.f32x2 %0, %1, %2, %0;" : "+l"(acc) : "l"(a), "l"(b))

__device__ __forceinline__ unsigned long long dupf32(float a) {
    unsigned long long r;
    asm("mov.b64 %0, {%1, %1};" : "=l"(r) : "f"(a));
    return r;
}
__device__ __forceinline__ void unpackf32(unsigned long long v, float& lo, float& hi) {
    asm("mov.b64 {%0, %1}, %2;" : "=f"(lo), "=f"(hi) : "l"(v));
}

// ---------------- SGEMM: C[M,128] = A[M,K] @ W[K,128] (+C if ACC) (+bias, relu if ACT) ----------------
template <int ACT, int ACC>
__global__ __launch_bounds__(256) void sgemm_kernel(
    const float* __restrict__ A, const float* __restrict__ W,
    const float* __restrict__ bias, float* __restrict__ C, int M, int K)
{
    __shared__ float As[BK][BM + 4];   // stored transposed: As[k][m]
    __shared__ float Bs[BK][BN];

    const int tid = threadIdx.x;
    const int m0 = blockIdx.x * BM;

    const int aRow = tid >> 2;            // 0..63
    const int aCol = (tid & 3) << 2;      // 0,4,8,12
    const int bRow = tid >> 5;            // 0..7
    const int bCol = (tid & 31) << 2;     // 0..124
    const int tr = tid >> 4;              // 0..15 -> rows tr*8..tr*8+7
    const int tc = tid & 15;              // 0..15 -> cols tc*8..tc*8+7

    unsigned long long acc[8][4];
#pragma unroll
    for (int i = 0; i < 8; i++)
#pragma unroll
        for (int j = 0; j < 4; j++) acc[i][j] = 0ULL;

    const int nkt = K / BK;
    for (int kt = 0; kt < nkt; kt++) {
        const int kb = kt * BK;
        float4 a0 = make_float4(0.f, 0.f, 0.f, 0.f), a1 = a0;
        if (m0 + aRow < M)      a0 = *(const float4*)(A + (size_t)(m0 + aRow) * K + kb + aCol);
        if (m0 + aRow + 64 < M) a1 = *(const float4*)(A + (size_t)(m0 + aRow + 64) * K + kb + aCol);
        const float4 b0 = *(const float4*)(W + (size_t)(kb + bRow) * 128 + bCol);
        const float4 b1 = *(const float4*)(W + (size_t)(kb + bRow + 8) * 128 + bCol);

        __syncthreads();   // previous iteration's compute done
        As[aCol + 0][aRow] = a0.x; As[aCol + 1][aRow] = a0.y;
        As[aCol + 2][aRow] = a0.z; As[aCol + 3][aRow] = a0.w;
        As[aCol + 0][aRow + 64] = a1.x; As[aCol + 1][aRow + 64] = a1.y;
        As[aCol + 2][aRow + 64] = a1.z; As[aCol + 3][aRow + 64] = a1.w;
        *(float4*)&Bs[bRow][bCol] = b0;
        *(float4*)&Bs[bRow + 8][bCol] = b1;
        __syncthreads();

#pragma unroll
        for (int k = 0; k < BK; k++) {
            const float4 af0 = *(const float4*)&As[k][tr * 8];
            const float4 af1 = *(const float4*)&As[k][tr * 8 + 4];
            const ulonglong2 bv0 = *(const ulonglong2*)&Bs[k][tc * 8];
            const ulonglong2 bv1 = *(const ulonglong2*)&Bs[k][tc * 8 + 4];
            const float av[8] = {af0.x, af0.y, af0.z, af0.w, af1.x, af1.y, af1.z, af1.w};
#pragma unroll
            for (int i = 0; i < 8; i++) {
                const unsigned long long ap = dupf32(av[i]);
                FMA2(acc[i][0], ap, bv0.x);
                FMA2(acc[i][1], ap, bv0.y);
                FMA2(acc[i][2], ap, bv1.x);
                FMA2(acc[i][3], ap, bv1.y);
            }
        }
    }

    const int col = tc * 8;
#pragma unroll
    for (int i = 0; i < 8; i++) {
        const int row = m0 + tr * 8 + i;
        if (row < M) {
            float v[8];
#pragma unroll
            for (int j = 0; j < 4; j++) unpackf32(acc[i][j], v[2 * j], v[2 * j + 1]);
            float* cp = C + (size_t)row * 128 + col;
            if (ACC) {
                const float4 o0 = *(const float4*)cp;
                const float4 o1 = *(const float4*)(cp + 4);
                v[0] += o0.x; v[1] += o0.y; v[2] += o0.z; v[3] += o0.w;
                v[4] += o1.x; v[5] += o1.y; v[6] += o1.z; v[7] += o1.w;
            }
            if (bias) {
#pragma unroll
                for (int j = 0; j < 8; j++) v[j] += __ldg(&bias[col + j]);
            }
            if (ACT) {
#pragma unroll
                for (int j = 0; j < 8; j++) v[j] = fmaxf(v[j], 0.f);
            }
            *(float4*)cp = make_float4(v[0], v[1], v[2], v[3]);
            *(float4*)(cp + 4) = make_float4(v[4], v[5], v[6], v[7]);
        }
    }
}

// ---------------- CSR build kernels ----------------
__global__ void zero_cnt_kernel() {
    const int i = blockIdx.x * blockDim.x + threadIdx.x;
    if (i < NN) g_cnt[i] = 0;
}

__global__ void degree_kernel(const void* __restrict__ ei) {
    const int i = blockIdx.x * blockDim.x + threadIdx.x;
    if (i < EE) {
        const int dst = load_idx(ei, (long long)EE + i, g_is64);
        if ((unsigned)dst < NN) atomicAdd(&g_cnt[dst], 1);
    }
}

// single-block scan over g_cnt -> g_rowptr/g_cur; also g_dinv = rsqrt(cnt+1)
__global__ void scan_kernel() {
    __shared__ int wsum[32];
    const int t = threadIdx.x, lane = t & 31, wid = t >> 5;
    int carry = 0;
    for (int base = 0; base < NN; base += 1024) {
        const int i = base + t;
        const int v = (i < NN) ? g_cnt[i] : 0;
        int x = v;
#pragma unroll
        for (int off = 1; off < 32; off <<= 1) {
            const int y = __shfl_up_sync(0xffffffffu, x, off);
            if (lane >= off) x += y;
        }
        if (lane == 31) wsum[wid] = x;
        __syncthreads();
        if (wid == 0) {
            int s = wsum[lane];
#pragma unroll
            for (int off = 1; off < 32; off <<= 1) {
                const int y = __shfl_up_sync(0xffffffffu, s, off);
                if (lane >= off) s += y;
            }
            wsum[lane] = s;
        }
        __syncthreads();
        const int woff = wid ? wsum[wid - 1] : 0;
        const int excl = carry + woff + x - v;
        if (i < NN) {
            g_rowptr[i] = excl;
            g_cur[i] = excl;
            g_dinv[i] = rsqrtf((float)v + 1.0f);
        }
        const int total = wsum[31];
        __syncthreads();
        carry += total;
    }
    if (t == 0) g_rowptr[NN] = carry;
}

__global__ void scatter_kernel(const void* __restrict__ ei) {
    const int i = blockIdx.x * blockDim.x + threadIdx.x;
    if (i < EE) {
        const int is64 = g_is64;
        const int dst = load_idx(ei, (long long)EE + i, is64);
        const int src = load_idx(ei, (long long)i, is64);
        if ((unsigned)dst < NN && (unsigned)src < NN) {
            const int pos = atomicAdd(&g_cur[dst], 1);
            if ((unsigned)pos < EE) g_srcidx[pos] = src;
        }
    }
}

// ---------------- GCN aggregation: out = relu(segsum(h[src]*norm) + self + bias) ----------------
__global__ __launch_bounds__(256) void aggregate_kernel(
    const float* __restrict__ h, const float* __restrict__ bias, float* __restrict__ out)
{
    const int gt = blockIdx.x * blockDim.x + threadIdx.x;
    const int node = gt >> 5, lane = gt & 31;
    if (node >= NN) return;
    const float di = g_dinv[node];
    const float4* __restrict__ hp = (const float4*)h;
    const float4 hv0 = hp[(size_t)node * 32 + lane];
    const float sw = di * di;   // self-loop norm
    float4 acc = make_float4(hv0.x * sw, hv0.y * sw, hv0.z * sw, hv0.w * sw);
    const int beg = g_rowptr[node], end = g_rowptr[node + 1];
    for (int e = beg; e < end; e++) {
        const int s = __ldg(&g_srcidx[e]);
        const float w = di * __ldg(&g_dinv[s]);
        const float4 hv = hp[(size_t)s * 32 + lane];
        acc.x = fmaf(hv.x, w, acc.x);
        acc.y = fmaf(hv.y, w, acc.y);
        acc.z = fmaf(hv.z, w, acc.z);
        acc.w = fmaf(hv.w, w, acc.w);
    }
    const float4 b = ((const float4*)bias)[lane];
    ((float4*)out)[(size_t)node * 32 + lane] =
        make_float4(fmaxf(acc.x + b.x, 0.f), fmaxf(acc.y + b.y, 0.f),
                    fmaxf(acc.z + b.z, 0.f), fmaxf(acc.w + b.w, 0.f));
}

// ---------------- final: sigmoid(comb @ out_W + out_b) ----------------
__global__ void final_kernel(const float* __restrict__ outW, const float* __restrict__ outb,
                             float* __restrict__ out)
{
    const int gt = blockIdx.x * blockDim.x + threadIdx.x;
    const int row = gt >> 5, lane = gt & 31;
    if (row >= NN) return;
    const float4 c = ((const float4*)g_comb)[(size_t)row * 32 + lane];
    const float4 w = ((const float4*)outW)[lane];
    float s = c.x * w.x + c.y * w.y + c.z * w.z + c.w * w.w;
#pragma unroll
    for (int off = 16; off; off >>= 1) s += __shfl_xor_sync(0xffffffffu, s, off);
    if (lane == 0) out[row] = 1.0f / (1.0f + expf(-(s + outb[0])));
}

// ---------------- orchestration ----------------
extern "C" void kernel_launch(void* const* d_in, const int* in_sizes, int n_in,
                              void* d_out, int out_size)
{
    const float* metadata_a = (const float*)d_in[0];
    const float* metadata_b = (const float*)d_in[1];
    const float* x_a        = (const float*)d_in[2];
    const float* x_b        = (const float*)d_in[3];
    const void*  ei_a       = d_in[4];
    const void*  ei_b       = d_in[5];
    const float* fc1_W  = (const float*)d_in[6];
    const float* fc1_b  = (const float*)d_in[7];
    const float* fc2_W  = (const float*)d_in[8];
    const float* fc2_b  = (const float*)d_in[9];
    const float* gcn1_W = (const float*)d_in[10];
    const float* gcn1_b = (const float*)d_in[11];
    const float* gcn2_W = (const float*)d_in[12];
    const float* gcn2_b = (const float*)d_in[13];
    const float* fcc_W  = (const float*)d_in[14];
    const float* fcc_b  = (const float*)d_in[15];
    const float* out_W  = (const float*)d_in[16];
    const float* out_b  = (const float*)d_in[17];
    float* out = (float*)d_out;

    float *p_ma, *p_mb, *p_ga, *p_gb, *p_h, *p_t, *p_comb;
    cudaGetSymbolAddress((void**)&p_ma, g_ma);
    cudaGetSymbolAddress((void**)&p_mb, g_mb);
    cudaGetSymbolAddress((void**)&p_ga, g_ga);
    cudaGetSymbolAddress((void**)&p_gb, g_gb);
    cudaGetSymbolAddress((void**)&p_h, g_h);
    cudaGetSymbolAddress((void**)&p_t, g_t);
    cudaGetSymbolAddress((void**)&p_comb, g_comb);

    const int GG = (NN + BM - 1) / BM;        // 391
    const int EB = (EE + 255) / 256;
    const int NB = (NN + 255) / 256;
    const int WB = (NN * 32 + 255) / 256;     // warp-per-node kernels

    detect_kernel<<<1, 32>>>((const unsigned int*)ei_a);

    // MLP branches
    sgemm_kernel<1, 0><<<GG, 256>>>(metadata_a, fc1_W, fc1_b, p_t, NN, 512);
    sgemm_kernel<1, 0><<<GG, 256>>>(p_t, fc2_W, fc2_b, p_ma, NN, 128);
    sgemm_kernel<1, 0><<<GG, 256>>>(metadata_b, fc1_W, fc1_b, p_t, NN, 512);
    sgemm_kernel<1, 0><<<GG, 256>>>(p_t, fc2_W, fc2_b, p_mb, NN, 128);

    // GCN branch, graph A
    zero_cnt_kernel<<<NB, 256>>>();
    degree_kernel<<<EB, 256>>>(ei_a);
    scan_kernel<<<1, 1024>>>();
    scatter_kernel<<<EB, 256>>>(ei_a);
    sgemm_kernel<0, 0><<<GG, 256>>>(x_a, gcn1_W, nullptr, p_h, NN, 256);
    aggregate_kernel<<<WB, 256>>>(p_h, gcn1_b, p_t);
    sgemm_kernel<0, 0><<<GG, 256>>>(p_t, gcn2_W, nullptr, p_h, NN, 128);
    aggregate_kernel<<<WB, 256>>>(p_h, gcn2_b, p_ga);

    // GCN branch, graph B
    zero_cnt_kernel<<<NB, 256>>>();
    degree_kernel<<<EB, 256>>>(ei_b);
    scan_kernel<<<1, 1024>>>();
    scatter_kernel<<<EB, 256>>>(ei_b);
    sgemm_kernel<0, 0><<<GG, 256>>>(x_b, gcn1_W, nullptr, p_h, NN, 256);
    aggregate_kernel<<<WB, 256>>>(p_h, gcn1_b, p_t);
    sgemm_kernel<0, 0><<<GG, 256>>>(p_t, gcn2_W, nullptr, p_h, NN, 128);
    aggregate_kernel<<<WB, 256>>>(p_h, gcn2_b, p_gb);

    // combined = [ma|mb|ga|gb] @ fcc_W (+bias, relu) as 4 accumulated K=128 GEMMs
    sgemm_kernel<0, 0><<<GG, 256>>>(p_ma, fcc_W,             nullptr, p_comb, NN, 128);
    sgemm_kernel<0, 1><<<GG, 256>>>(p_mb, fcc_W + 128 * 128, nullptr, p_comb, NN, 128);
    sgemm_kernel<0, 1><<<GG, 256>>>(p_ga, fcc_W + 256 * 128, nullptr, p_comb, NN, 128);
    sgemm_kernel<1, 1><<<GG, 256>>>(p_gb, fcc_W + 384 * 128, fcc_b,   p_comb, NN, 128);

    final_kernel<<<WB, 256>>>(out_W, out_b, out);
}

// round 4
// speedup vs baseline: 1.4461x; 1.4461x over previous
#include <cuda_runtime.h>
#include <cuda_bf16.h>
#include <cstdint>

#define NN 50000
#define EE 1600000

// ---------------- device scratch (no allocs allowed) ----------------
__device__ __align__(256) float g_cat[NN * 512];   // [ma | mb | ga | gb] concat, ld=512
__device__ __align__(256) float g_h[NN * 128];
__device__ __align__(256) float g_t[NN * 128];
__device__ __align__(256) float g_comb[NN * 128];
__device__ int   g_cnt[NN];
__device__ float g_dinv[NN];
__device__ int   g_rowptr[NN + 1];
__device__ int   g_cur[NN];
__device__ int   g_srcidx[EE];
__device__ int   g_is64;

// ---------------- helpers ----------------
__device__ __forceinline__ uint32_t smem_to_u32(const void* p) {
    uint32_t a;
    asm("{ .reg .u64 t; cvta.to.shared.u64 t, %1; cvt.u32.u64 %0, t; }" : "=r"(a) : "l"(p));
    return a;
}

__device__ __forceinline__ unsigned long long pack4bf(float a, float b, float c, float d) {
    unsigned short u0 = __bfloat16_as_ushort(__float2bfloat16(a));
    unsigned short u1 = __bfloat16_as_ushort(__float2bfloat16(b));
    unsigned short u2 = __bfloat16_as_ushort(__float2bfloat16(c));
    unsigned short u3 = __bfloat16_as_ushort(__float2bfloat16(d));
    return (unsigned long long)u0 | ((unsigned long long)u1 << 16) |
           ((unsigned long long)u2 << 32) | ((unsigned long long)u3 << 48);
}
__device__ __forceinline__ float bf_res(float a) {
    return a - __bfloat162float(__float2bfloat16(a));
}

#define LDSM_X4(d, a) \
    asm volatile("ldmatrix.sync.aligned.m8n8.x4.shared.b16 {%0,%1,%2,%3}, [%4];" \
        : "=r"((d)[0]), "=r"((d)[1]), "=r"((d)[2]), "=r"((d)[3]) : "r"(a))
#define LDSM_X4_T(d, a) \
    asm volatile("ldmatrix.sync.aligned.m8n8.x4.trans.shared.b16 {%0,%1,%2,%3}, [%4];" \
        : "=r"((d)[0]), "=r"((d)[1]), "=r"((d)[2]), "=r"((d)[3]) : "r"(a))
#define MMA_BF16(c, a, b0, b1) \
    asm volatile("mma.sync.aligned.m16n8k16.row.col.f32.bf16.bf16.f32 " \
        "{%0,%1,%2,%3}, {%4,%5,%6,%7}, {%8,%9}, {%0,%1,%2,%3};" \
        : "+f"((c)[0]), "+f"((c)[1]), "+f"((c)[2]), "+f"((c)[3]) \
        : "r"((a)[0]), "r"((a)[1]), "r"((a)[2]), "r"((a)[3]), "r"(b0), "r"(b1))

// smem: per buffer: A_hi 128x40bf16(10240B) | A_lo(10240) | B_hi 32x136bf16(8704) | B_lo(8704)
#define BUF_STRIDE 37888
#define OFF_ALO 10240
#define OFF_BHI 20480
#define OFF_BLO 29184
#define SMEM_DYN (2 * BUF_STRIDE)

// ---------------- HMMA split-bf16 GEMM: C[M,128] = A[M,K] @ W[K,128] ----------------
template <int ACT>
__global__ __launch_bounds__(512) void mma_gemm(
    const float* __restrict__ A, int lda, const float* __restrict__ W,
    const float* __restrict__ bias, float* __restrict__ C, int ldc, int M, int K)
{
    extern __shared__ char smem[];
    const uint32_t sb = smem_to_u32(smem);
    const int tid = threadIdx.x, wid = tid >> 5, lane = tid & 31;
    const int m0 = blockIdx.x * 128;
    const int m_off = (wid & 3) * 32, n_off = (wid >> 2) * 32;

    // ldmatrix lane address components
    const int mi = lane >> 3, r8 = lane & 7;
    const int aRowL = m_off + (mi & 1) * 8 + r8;   // + mt*16
    const int aColL = (mi >> 1) * 8;               // + k16*16
    const int bRowL = (mi & 1) * 8 + r8;           // + k16*16
    const int bColL = n_off + (mi >> 1) * 8;       // + nt*16

    // global prefetch mapping: 2 float4 per thread for A and B
    int aRow[2], aK[2], bRow[2], bN[2];
#pragma unroll
    for (int i = 0; i < 2; i++) {
        const int f = tid * 2 + i;
        aRow[i] = f >> 3; aK[i] = (f & 7) * 4;
        bRow[i] = f >> 5; bN[i] = (f & 31) * 4;
    }

    float acc[2][4][4];
#pragma unroll
    for (int mt = 0; mt < 2; mt++)
#pragma unroll
        for (int nt = 0; nt < 4; nt++)
#pragma unroll
            for (int j = 0; j < 4; j++) acc[mt][nt][j] = 0.f;

    float4 ra[2], rb[2];
    const int nch = K >> 5;

    auto gload = [&](int c) {
#pragma unroll
        for (int i = 0; i < 2; i++) {
            ra[i] = make_float4(0.f, 0.f, 0.f, 0.f);
            if (m0 + aRow[i] < M)
                ra[i] = *(const float4*)(A + (size_t)(m0 + aRow[i]) * lda + c * 32 + aK[i]);
            rb[i] = *(const float4*)(W + (size_t)(c * 32 + bRow[i]) * 128 + bN[i]);
        }
    };
    auto sstore = [&](int b) {
        char* base = smem + b * BUF_STRIDE;
#pragma unroll
        for (int i = 0; i < 2; i++) {
            const uint32_t off = (uint32_t)(aRow[i] * 80 + aK[i] * 2);
            *(unsigned long long*)(base + off) = pack4bf(ra[i].x, ra[i].y, ra[i].z, ra[i].w);
            *(unsigned long long*)(base + OFF_ALO + off) =
                pack4bf(bf_res(ra[i].x), bf_res(ra[i].y), bf_res(ra[i].z), bf_res(ra[i].w));
            const uint32_t boff = (uint32_t)(bRow[i] * 272 + bN[i] * 2);
            *(unsigned long long*)(base + OFF_BHI + boff) = pack4bf(rb[i].x, rb[i].y, rb[i].z, rb[i].w);
            *(unsigned long long*)(base + OFF_BLO + boff) =
                pack4bf(bf_res(rb[i].x), bf_res(rb[i].y), bf_res(rb[i].z), bf_res(rb[i].w));
        }
    };
    auto compute = [&](int b) {
        const uint32_t aH = sb + b * BUF_STRIDE;
        const uint32_t aL = aH + OFF_ALO;
        const uint32_t bH = aH + OFF_BHI;
#pragma unroll
        for (int k16 = 0; k16 < 2; k16++) {
            uint32_t ah[2][4], bh[2][4], bl[2][4];
#pragma unroll
            for (int mt = 0; mt < 2; mt++)
                LDSM_X4(ah[mt], aH + (uint32_t)(((aRowL + mt * 16) * 40 + aColL + k16 * 16) * 2));
#pragma unroll
            for (int nt = 0; nt < 2; nt++) {
                const uint32_t ba = bH +
                    (uint32_t)(((bRowL + k16 * 16) * 136 + bColL + nt * 16) * 2);
                LDSM_X4_T(bh[nt], ba);
                LDSM_X4_T(bl[nt], ba + (OFF_BLO - OFF_BHI));
            }
#pragma unroll
            for (int mt = 0; mt < 2; mt++)
#pragma unroll
                for (int nt = 0; nt < 2; nt++) {
                    MMA_BF16(acc[mt][nt * 2 + 0], ah[mt], bh[nt][0], bh[nt][1]);
                    MMA_BF16(acc[mt][nt * 2 + 1], ah[mt], bh[nt][2], bh[nt][3]);
                    MMA_BF16(acc[mt][nt * 2 + 0], ah[mt], bl[nt][0], bl[nt][1]);
                    MMA_BF16(acc[mt][nt * 2 + 1], ah[mt], bl[nt][2], bl[nt][3]);
                }
#pragma unroll
            for (int mt = 0; mt < 2; mt++)
                LDSM_X4(ah[mt], aL + (uint32_t)(((aRowL + mt * 16) * 40 + aColL + k16 * 16) * 2));
#pragma unroll
            for (int mt = 0; mt < 2; mt++)
#pragma unroll
                for (int nt = 0; nt < 2; nt++) {
                    MMA_BF16(acc[mt][nt * 2 + 0], ah[mt], bh[nt][0], bh[nt][1]);
                    MMA_BF16(acc[mt][nt * 2 + 1], ah[mt], bh[nt][2], bh[nt][3]);
                }
        }
    };

    gload(0);
    sstore(0);
    __syncthreads();
    for (int c = 0; c < nch; c++) {
        if (c + 1 < nch) gload(c + 1);
        compute(c & 1);
        if (c + 1 < nch) {
            __syncthreads();
            sstore((c + 1) & 1);
            __syncthreads();
        }
    }

    // epilogue: acc frag (mt, n8-chunk nt): lane l -> rows +l>>2, +8; cols nt*8 + 2(l&3)
    const int er = lane >> 2, ec = (lane & 3) * 2;
#pragma unroll
    for (int mt = 0; mt < 2; mt++) {
        const int row0 = m0 + m_off + mt * 16 + er;
#pragma unroll
        for (int nt = 0; nt < 4; nt++) {
            const int col = n_off + nt * 8 + ec;
            float b0 = 0.f, b1 = 0.f;
            if (bias) { b0 = __ldg(&bias[col]); b1 = __ldg(&bias[col + 1]); }
            float v0 = acc[mt][nt][0] + b0, v1 = acc[mt][nt][1] + b1;
            float v2 = acc[mt][nt][2] + b0, v3 = acc[mt][nt][3] + b1;
            if (ACT) {
                v0 = fmaxf(v0, 0.f); v1 = fmaxf(v1, 0.f);
                v2 = fmaxf(v2, 0.f); v3 = fmaxf(v3, 0.f);
            }
            if (row0 < M) *(float2*)(C + (size_t)row0 * ldc + col) = make_float2(v0, v1);
            if (row0 + 8 < M) *(float2*)(C + (size_t)(row0 + 8) * ldc + col) = make_float2(v2, v3);
        }
    }
}

// ---------------- edge-index dtype detection ----------------
__global__ void detect_kernel(const unsigned int* __restrict__ w) {
    if (threadIdx.x == 0 && blockIdx.x == 0) {
        int zeros = 0;
        for (int i = 1; i < 512; i += 2) zeros += (w[i] == 0u) ? 1 : 0;
        g_is64 = (zeros >= 200) ? 1 : 0;
    }
}
__device__ __forceinline__ int load_idx(const void* ei, long long pos, int is64) {
    if (is64) return (int)((const long long*)ei)[pos];
    return ((const int*)ei)[pos];
}

// ---------------- CSR build kernels ----------------
__global__ void zero_cnt_kernel() {
    const int i = blockIdx.x * blockDim.x + threadIdx.x;
    if (i < NN) g_cnt[i] = 0;
}
__global__ void degree_kernel(const void* __restrict__ ei) {
    const int i = blockIdx.x * blockDim.x + threadIdx.x;
    if (i < EE) {
        const int dst = load_idx(ei, (long long)EE + i, g_is64);
        if ((unsigned)dst < NN) atomicAdd(&g_cnt[dst], 1);
    }
}
__global__ void scan_kernel() {
    __shared__ int wsum[32];
    const int t = threadIdx.x, lane = t & 31, wid = t >> 5;
    int carry = 0;
    for (int base = 0; base < NN; base += 1024) {
        const int i = base + t;
        const int v = (i < NN) ? g_cnt[i] : 0;
        int x = v;
#pragma unroll
        for (int off = 1; off < 32; off <<= 1) {
            const int y = __shfl_up_sync(0xffffffffu, x, off);
            if (lane >= off) x += y;
        }
        if (lane == 31) wsum[wid] = x;
        __syncthreads();
        if (wid == 0) {
            int s = wsum[lane];
#pragma unroll
            for (int off = 1; off < 32; off <<= 1) {
                const int y = __shfl_up_sync(0xffffffffu, s, off);
                if (lane >= off) s += y;
            }
            wsum[lane] = s;
        }
        __syncthreads();
        const int woff = wid ? wsum[wid - 1] : 0;
        const int excl = carry + woff + x - v;
        if (i < NN) {
            g_rowptr[i] = excl;
            g_cur[i] = excl;
            g_dinv[i] = rsqrtf((float)v + 1.0f);
        }
        const int total = wsum[31];
        __syncthreads();
        carry += total;
    }
    if (t == 0) g_rowptr[NN] = carry;
}
__global__ void scatter_kernel(const void* __restrict__ ei) {
    const int i = blockIdx.x * blockDim.x + threadIdx.x;
    if (i < EE) {
        const int is64 = g_is64;
        const int dst = load_idx(ei, (long long)EE + i, is64);
        const int src = load_idx(ei, (long long)i, is64);
        if ((unsigned)dst < NN && (unsigned)src < NN) {
            const int pos = atomicAdd(&g_cur[dst], 1);
            if ((unsigned)pos < EE) g_srcidx[pos] = src;
        }
    }
}

// ---------------- GCN aggregation (strided output) ----------------
__global__ __launch_bounds__(256) void aggregate_kernel(
    const float* __restrict__ h, const float* __restrict__ bias,
    float* __restrict__ out, int ldo)
{
    const int gt = blockIdx.x * blockDim.x + threadIdx.x;
    const int node = gt >> 5, lane = gt & 31;
    if (node >= NN) return;
    const float di = g_dinv[node];
    const float4* __restrict__ hp = (const float4*)h;
    const float4 hv0 = hp[(size_t)node * 32 + lane];
    const float sw = di * di;
    float4 acc = make_float4(hv0.x * sw, hv0.y * sw, hv0.z * sw, hv0.w * sw);
    const int beg = g_rowptr[node], end = g_rowptr[node + 1];
    for (int e = beg; e < end; e++) {
        const int s = __ldg(&g_srcidx[e]);
        const float w = di * __ldg(&g_dinv[s]);
        const float4 hv = hp[(size_t)s * 32 + lane];
        acc.x = fmaf(hv.x, w, acc.x);
        acc.y = fmaf(hv.y, w, acc.y);
        acc.z = fmaf(hv.z, w, acc.z);
        acc.w = fmaf(hv.w, w, acc.w);
    }
    const float4 b = ((const float4*)bias)[lane];
    *(float4*)(out + (size_t)node * ldo + lane * 4) =
        make_float4(fmaxf(acc.x + b.x, 0.f), fmaxf(acc.y + b.y, 0.f),
                    fmaxf(acc.z + b.z, 0.f), fmaxf(acc.w + b.w, 0.f));
}

// ---------------- final: sigmoid(comb @ out_W + out_b) ----------------
__global__ void final_kernel(const float* __restrict__ outW, const float* __restrict__ outb,
                             float* __restrict__ out)
{
    const int gt = blockIdx.x * blockDim.x + threadIdx.x;
    const int row = gt >> 5, lane = gt & 31;
    if (row >= NN) return;
    const float4 c = ((const float4*)g_comb)[(size_t)row * 32 + lane];
    const float4 w = ((const float4*)outW)[lane];
    float s = c.x * w.x + c.y * w.y + c.z * w.z + c.w * w.w;
#pragma unroll
    for (int off = 16; off; off >>= 1) s += __shfl_xor_sync(0xffffffffu, s, off);
    if (lane == 0) out[row] = 1.0f / (1.0f + expf(-(s + outb[0])));
}

// ---------------- orchestration ----------------
extern "C" void kernel_launch(void* const* d_in, const int* in_sizes, int n_in,
                              void* d_out, int out_size)
{
    const float* metadata_a = (const float*)d_in[0];
    const float* metadata_b = (const float*)d_in[1];
    const float* x_a        = (const float*)d_in[2];
    const float* x_b        = (const float*)d_in[3];
    const void*  ei_a       = d_in[4];
    const void*  ei_b       = d_in[5];
    const float* fc1_W  = (const float*)d_in[6];
    const float* fc1_b  = (const float*)d_in[7];
    const float* fc2_W  = (const float*)d_in[8];
    const float* fc2_b  = (const float*)d_in[9];
    const float* gcn1_W = (const float*)d_in[10];
    const float* gcn1_b = (const float*)d_in[11];
    const float* gcn2_W = (const float*)d_in[12];
    const float* gcn2_b = (const float*)d_in[13];
    const float* fcc_W  = (const float*)d_in[14];
    const float* fcc_b  = (const float*)d_in[15];
    const float* out_W  = (const float*)d_in[16];
    const float* out_b  = (const float*)d_in[17];
    float* out = (float*)d_out;

    float *p_cat, *p_h, *p_t, *p_comb;
    cudaGetSymbolAddress((void**)&p_cat, g_cat);
    cudaGetSymbolAddress((void**)&p_h, g_h);
    cudaGetSymbolAddress((void**)&p_t, g_t);
    cudaGetSymbolAddress((void**)&p_comb, g_comb);

    cudaFuncSetAttribute(mma_gemm<0>, cudaFuncAttributeMaxDynamicSharedMemorySize, SMEM_DYN);
    cudaFuncSetAttribute(mma_gemm<1>, cudaFuncAttributeMaxDynamicSharedMemorySize, SMEM_DYN);

    const int GG = (NN + 127) / 128;          // 391
    const int EB = (EE + 255) / 256;
    const int NB = (NN + 255) / 256;
    const int WB = (NN * 32 + 255) / 256;

    detect_kernel<<<1, 32>>>((const unsigned int*)ei_a);

    // MLP branches -> g_cat[:, 0:128] and [:, 128:256]
    mma_gemm<1><<<GG, 512, SMEM_DYN>>>(metadata_a, 512, fc1_W, fc1_b, p_t, 128, NN, 512);
    mma_gemm<1><<<GG, 512, SMEM_DYN>>>(p_t, 128, fc2_W, fc2_b, p_cat + 0, 512, NN, 128);
    mma_gemm<1><<<GG, 512, SMEM_DYN>>>(metadata_b, 512, fc1_W, fc1_b, p_t, 128, NN, 512);
    mma_gemm<1><<<GG, 512, SMEM_DYN>>>(p_t, 128, fc2_W, fc2_b, p_cat + 128, 512, NN, 128);

    // GCN branch, graph A -> g_cat[:, 256:384]
    zero_cnt_kernel<<<NB, 256>>>();
    degree_kernel<<<EB, 256>>>(ei_a);
    scan_kernel<<<1, 1024>>>();
    scatter_kernel<<<EB, 256>>>(ei_a);
    mma_gemm<0><<<GG, 512, SMEM_DYN>>>(x_a, 256, gcn1_W, nullptr, p_h, 128, NN, 256);
    aggregate_kernel<<<WB, 256>>>(p_h, gcn1_b, p_t, 128);
    mma_gemm<0><<<GG, 512, SMEM_DYN>>>(p_t, 128, gcn2_W, nullptr, p_h, 128, NN, 128);
    aggregate_kernel<<<WB, 256>>>(p_h, gcn2_b, p_cat + 256, 512);

    // GCN branch, graph B -> g_cat[:, 384:512]
    zero_cnt_kernel<<<NB, 256>>>();
    degree_kernel<<<EB, 256>>>(ei_b);
    scan_kernel<<<1, 1024>>>();
    scatter_kernel<<<EB, 256>>>(ei_b);
    mma_gemm<0><<<GG, 512, SMEM_DYN>>>(x_b, 256, gcn1_W, nullptr, p_h, 128, NN, 256);
    aggregate_kernel<<<WB, 256>>>(p_h, gcn1_b, p_t, 128);
    mma_gemm<0><<<GG, 512, SMEM_DYN>>>(p_t, 128, gcn2_W, nullptr, p_h, 128, NN, 128);
    aggregate_kernel<<<WB, 256>>>(p_h, gcn2_b, p_cat + 384, 512);

    // combined = relu(cat @ fcc_W + b), single K=512 GEMM
    mma_gemm<1><<<GG, 512, SMEM_DYN>>>(p_cat, 512, fcc_W, fcc_b, p_comb, 128, NN, 512);

    final_kernel<<<WB, 256>>>(out_W, out_b, out);
}